// round 1
// baseline (speedup 1.0000x reference)
#include <cuda_runtime.h>

#define BB 64
#define DD 512
#define TT 50
#define SS 400
#define KK 50

// ------------------- device scratch (no allocations allowed) -------------------
__device__ float g_pre[BB * SS * DD];    // 52.4 MB  [B, S, D]
__device__ float g_tpre[BB * KK * DD];   //  6.6 MB  [B, K, D]
__device__ float g_h0[2][BB * DD];
__device__ float g_h1[2][BB * DD];
__device__ float g_mix[BB * DD];
__device__ float g_emb[BB * DD];
__device__ float g_q[BB * DD];
__device__ float g_tq[BB * DD];
__device__ float g_gate[BB];

__device__ __forceinline__ float sigmoidf_(float x) { return 1.0f / (1.0f + __expf(-x)); }
__device__ __forceinline__ float tanh_fast(float x) {
    float y;
    asm("tanh.approx.f32 %0, %1;" : "=f"(y) : "f"(x));
    return y;
}

// ------------------- init -------------------
__global__ void init_state(const float* __restrict__ hidden, const float* __restrict__ mix_init) {
    int i = blockIdx.x * blockDim.x + threadIdx.x;
    if (i < BB * DD) {
        g_h0[0][i] = hidden[i];
        g_h1[0][i] = hidden[BB * DD + i];
        g_mix[i]   = mix_init[i];
    }
}

// ------------------- pre = ctx @ W^T + b  (ctx is [L,B,D], out is [B,L,D]) -------------------
__global__ void precompute_kernel(const float* __restrict__ ctx, const float* __restrict__ W,
                                  const float* __restrict__ bias, int L, int topic) {
    int b = blockIdx.x / L;
    int l = blockIdx.x % L;
    __shared__ float xs[DD];
    const float* x = ctx + ((size_t)l * BB + b) * DD;
    for (int i = threadIdx.x; i < DD; i += 128) xs[i] = x[i];
    __syncthreads();
    int j = threadIdx.x;
    const float* w0 = W + (size_t)j * DD;
    const float* w1 = W + (size_t)(j + 128) * DD;
    const float* w2 = W + (size_t)(j + 256) * DD;
    const float* w3 = W + (size_t)(j + 384) * DD;
    float a0 = 0.f, a1 = 0.f, a2 = 0.f, a3 = 0.f;
#pragma unroll 4
    for (int k = 0; k < DD; k += 4) {
        float4 xv = *(const float4*)(xs + k);
        float4 u0 = *(const float4*)(w0 + k);
        float4 u1 = *(const float4*)(w1 + k);
        float4 u2 = *(const float4*)(w2 + k);
        float4 u3 = *(const float4*)(w3 + k);
        a0 += xv.x * u0.x + xv.y * u0.y + xv.z * u0.z + xv.w * u0.w;
        a1 += xv.x * u1.x + xv.y * u1.y + xv.z * u1.z + xv.w * u1.w;
        a2 += xv.x * u2.x + xv.y * u2.y + xv.z * u2.z + xv.w * u2.w;
        a3 += xv.x * u3.x + xv.y * u3.y + xv.z * u3.z + xv.w * u3.w;
    }
    float* out = (topic ? g_tpre : g_pre) + ((size_t)b * L + l) * DD;
    out[j]       = a0 + bias[j];
    out[j + 128] = a1 + bias[j + 128];
    out[j + 256] = a2 + bias[j + 256];
    out[j + 384] = a3 + bias[j + 384];
}

// ------------------- GRU layer 0: x = [emb_t, mix] (1024) -------------------
__global__ void gru0_kernel(const int* __restrict__ tgt, const float* __restrict__ emb_table,
                            const float* __restrict__ W_ih, const float* __restrict__ W_hh,
                            const float* __restrict__ b_ih, const float* __restrict__ b_hh, int t) {
    int b = blockIdx.x;
    int cur = t & 1, nxt = cur ^ 1;
    __shared__ float xs[2 * DD];
    __shared__ float hs[DD];
    int tok = tgt[t * BB + b];
    const float* erow = emb_table + (size_t)tok * DD;
    for (int i = threadIdx.x; i < DD; i += 128) {
        float e = erow[i];
        xs[i]      = e;
        xs[DD + i] = g_mix[b * DD + i];
        hs[i]      = g_h0[cur][b * DD + i];
        if (blockIdx.y == 0) g_emb[b * DD + i] = e;
    }
    __syncthreads();
    int j = blockIdx.y * 128 + threadIdx.x;
    float ar = b_ih[j], az = b_ih[j + DD], an = b_ih[j + 2 * DD];
    {
        const float* wr = W_ih + (size_t)j * (2 * DD);
        const float* wz = W_ih + (size_t)(j + DD) * (2 * DD);
        const float* wn = W_ih + (size_t)(j + 2 * DD) * (2 * DD);
#pragma unroll 2
        for (int k = 0; k < 2 * DD; k += 4) {
            float4 xv = *(const float4*)(xs + k);
            float4 r4 = *(const float4*)(wr + k);
            float4 z4 = *(const float4*)(wz + k);
            float4 n4 = *(const float4*)(wn + k);
            ar += xv.x * r4.x + xv.y * r4.y + xv.z * r4.z + xv.w * r4.w;
            az += xv.x * z4.x + xv.y * z4.y + xv.z * z4.z + xv.w * z4.w;
            an += xv.x * n4.x + xv.y * n4.y + xv.z * n4.z + xv.w * n4.w;
        }
    }
    float hr = b_hh[j], hz = b_hh[j + DD], hn = b_hh[j + 2 * DD];
    {
        const float* wr = W_hh + (size_t)j * DD;
        const float* wz = W_hh + (size_t)(j + DD) * DD;
        const float* wn = W_hh + (size_t)(j + 2 * DD) * DD;
#pragma unroll 2
        for (int k = 0; k < DD; k += 4) {
            float4 xv = *(const float4*)(hs + k);
            float4 r4 = *(const float4*)(wr + k);
            float4 z4 = *(const float4*)(wz + k);
            float4 n4 = *(const float4*)(wn + k);
            hr += xv.x * r4.x + xv.y * r4.y + xv.z * r4.z + xv.w * r4.w;
            hz += xv.x * z4.x + xv.y * z4.y + xv.z * z4.z + xv.w * z4.w;
            hn += xv.x * n4.x + xv.y * n4.y + xv.z * n4.z + xv.w * n4.w;
        }
    }
    float r = sigmoidf_(ar + hr);
    float z = sigmoidf_(az + hz);
    float n = tanhf(an + r * hn);
    g_h0[nxt][b * DD + j] = (1.0f - z) * n + z * hs[j];
}

// ------------------- GRU layer 1: x = h0_new (512) -------------------
__global__ void gru1_kernel(const float* __restrict__ W_ih, const float* __restrict__ W_hh,
                            const float* __restrict__ b_ih, const float* __restrict__ b_hh, int t) {
    int b = blockIdx.x;
    int cur = t & 1, nxt = cur ^ 1;
    __shared__ float xs[DD];
    __shared__ float hs[DD];
    for (int i = threadIdx.x; i < DD; i += 128) {
        xs[i] = g_h0[nxt][b * DD + i];
        hs[i] = g_h1[cur][b * DD + i];
    }
    __syncthreads();
    int j = blockIdx.y * 128 + threadIdx.x;
    float ar = b_ih[j], az = b_ih[j + DD], an = b_ih[j + 2 * DD];
    {
        const float* wr = W_ih + (size_t)j * DD;
        const float* wz = W_ih + (size_t)(j + DD) * DD;
        const float* wn = W_ih + (size_t)(j + 2 * DD) * DD;
#pragma unroll 2
        for (int k = 0; k < DD; k += 4) {
            float4 xv = *(const float4*)(xs + k);
            float4 r4 = *(const float4*)(wr + k);
            float4 z4 = *(const float4*)(wz + k);
            float4 n4 = *(const float4*)(wn + k);
            ar += xv.x * r4.x + xv.y * r4.y + xv.z * r4.z + xv.w * r4.w;
            az += xv.x * z4.x + xv.y * z4.y + xv.z * z4.z + xv.w * z4.w;
            an += xv.x * n4.x + xv.y * n4.y + xv.z * n4.z + xv.w * n4.w;
        }
    }
    float hr = b_hh[j], hz = b_hh[j + DD], hn = b_hh[j + 2 * DD];
    {
        const float* wr = W_hh + (size_t)j * DD;
        const float* wz = W_hh + (size_t)(j + DD) * DD;
        const float* wn = W_hh + (size_t)(j + 2 * DD) * DD;
#pragma unroll 2
        for (int k = 0; k < DD; k += 4) {
            float4 xv = *(const float4*)(hs + k);
            float4 r4 = *(const float4*)(wr + k);
            float4 z4 = *(const float4*)(wz + k);
            float4 n4 = *(const float4*)(wn + k);
            hr += xv.x * r4.x + xv.y * r4.y + xv.z * r4.z + xv.w * r4.w;
            hz += xv.x * z4.x + xv.y * z4.y + xv.z * z4.z + xv.w * z4.w;
            hn += xv.x * n4.x + xv.y * n4.y + xv.z * n4.z + xv.w * n4.w;
        }
    }
    float r = sigmoidf_(ar + hr);
    float z = sigmoidf_(az + hz);
    float n = tanhf(an + r * hn);
    g_h1[nxt][b * DD + j] = (1.0f - z) * n + z * hs[j];
}

// ------------------- q / tq projections + gate -------------------
__global__ void qproj_kernel(const float* __restrict__ qW, const float* __restrict__ tqW,
                             const float* __restrict__ gW, const float* __restrict__ gb,
                             float* __restrict__ gate_out, int t) {
    int b = blockIdx.x, y = blockIdx.y;  // y in [0,8): 0-3 -> q, 4-7 -> tq
    int nxt = (t & 1) ^ 1;
    __shared__ float os[DD];
    for (int i = threadIdx.x; i < DD; i += 128) os[i] = g_h1[nxt][b * DD + i];
    __syncthreads();
    const float* W = (y < 4) ? qW : tqW;
    int j = (y & 3) * 128 + threadIdx.x;
    const float* w = W + (size_t)j * DD;
    float acc = 0.f;
#pragma unroll 4
    for (int k = 0; k < DD; k += 4) {
        float4 xv = *(const float4*)(os + k);
        float4 wv = *(const float4*)(w + k);
        acc += xv.x * wv.x + xv.y * wv.y + xv.z * wv.z + xv.w * wv.w;
    }
    ((y < 4) ? g_q : g_tq)[b * DD + j] = acc;
    if (y == 0) {
        __shared__ float red[128];
        int k0 = threadIdx.x * 4;
        float4 xv = *(const float4*)(os + k0);
        float4 wv = *(const float4*)(gW + k0);
        red[threadIdx.x] = xv.x * wv.x + xv.y * wv.y + xv.z * wv.z + xv.w * wv.w;
        __syncthreads();
        for (int s = 64; s; s >>= 1) {
            if (threadIdx.x < s) red[threadIdx.x] += red[threadIdx.x + s];
            __syncthreads();
        }
        if (threadIdx.x == 0) {
            float g = sigmoidf_(red[0] + gb[0]);
            g_gate[b] = g;
            gate_out[t * BB + b] = g;
        }
    }
}

// ------------------- energy + softmax (src: y=0, topic: y=1) -------------------
__global__ void attn_kernel(const float* __restrict__ v, const float* __restrict__ tv,
                            const float* __restrict__ smask, const float* __restrict__ tmask,
                            float* __restrict__ attn_out, float* __restrict__ tattn_out, int t) {
    int b = blockIdx.x;
    bool topic = (blockIdx.y == 1);
    int L = topic ? KK : SS;
    const float* pre = topic ? (g_tpre + (size_t)b * KK * DD) : (g_pre + (size_t)b * SS * DD);
    const float* qq  = (topic ? g_tq : g_q) + b * DD;
    const float* vv  = topic ? tv : v;
    const float* mk  = topic ? (tmask + b * KK) : (smask + b * SS);
    float* aout = topic ? (tattn_out + (size_t)t * BB * KK + (size_t)b * KK)
                        : (attn_out + (size_t)t * BB * SS + (size_t)b * SS);
    __shared__ float qs[DD], vs[DD], es[SS];
    __shared__ float sred[16];
    int tid = threadIdx.x, warp = tid >> 5, lane = tid & 31;
    for (int i = tid; i < DD; i += 512) { qs[i] = qq[i]; vs[i] = vv[i]; }
    __syncthreads();
    for (int l = warp; l < L; l += 16) {
        const float* pr = pre + (size_t)l * DD;
        float e = 0.f;
#pragma unroll
        for (int c = 0; c < 4; c++) {
            int a = c * 128 + lane * 4;
            float4 p  = *(const float4*)(pr + a);
            float4 q4 = *(const float4*)(qs + a);
            float4 v4 = *(const float4*)(vs + a);
            e += tanh_fast(p.x + q4.x) * v4.x;
            e += tanh_fast(p.y + q4.y) * v4.y;
            e += tanh_fast(p.z + q4.z) * v4.z;
            e += tanh_fast(p.w + q4.w) * v4.w;
        }
#pragma unroll
        for (int o = 16; o; o >>= 1) e += __shfl_xor_sync(0xffffffffu, e, o);
        if (lane == 0) es[l] = (mk[l] > 0.5f) ? -1e6f : e;
    }
    __syncthreads();
    // block softmax over es[0..L)
    float m = -3.4e38f;
    for (int i = tid; i < L; i += 512) m = fmaxf(m, es[i]);
#pragma unroll
    for (int o = 16; o; o >>= 1) m = fmaxf(m, __shfl_xor_sync(0xffffffffu, m, o));
    if (lane == 0) sred[warp] = m;
    __syncthreads();
    float bm = sred[0];
#pragma unroll
    for (int w = 1; w < 16; w++) bm = fmaxf(bm, sred[w]);
    __syncthreads();
    float s = 0.f;
    for (int i = tid; i < L; i += 512) {
        float ex = __expf(es[i] - bm);
        es[i] = ex;
        s += ex;
    }
#pragma unroll
    for (int o = 16; o; o >>= 1) s += __shfl_xor_sync(0xffffffffu, s, o);
    if (lane == 0) sred[warp] = s;
    __syncthreads();
    float bs = 0.f;
#pragma unroll
    for (int w = 0; w < 16; w++) bs += sred[w];
    float inv = 1.0f / bs;
    for (int i = tid; i < L; i += 512) aout[i] = es[i] * inv;
}

// ------------------- weighted contexts + gated mix -------------------
__global__ void ctxmix_kernel(const float* __restrict__ context, const float* __restrict__ tcontext,
                              const float* __restrict__ attn_out, const float* __restrict__ tattn_out,
                              int t) {
    int b = blockIdx.x;
    int d = blockIdx.y * 128 + threadIdx.x;
    __shared__ float as[SS];
    __shared__ float tas[KK];
    const float* a  = attn_out + (size_t)t * BB * SS + (size_t)b * SS;
    const float* ta = tattn_out + (size_t)t * BB * KK + (size_t)b * KK;
    for (int i = threadIdx.x; i < SS; i += 128) as[i] = a[i];
    for (int i = threadIdx.x; i < KK; i += 128) tas[i] = ta[i];
    __syncthreads();
    const float* cb = context + (size_t)b * DD + d;
    float c = 0.f;
#pragma unroll 8
    for (int l = 0; l < SS; l++) c += as[l] * cb[(size_t)l * BB * DD];
    const float* tcb = tcontext + (size_t)b * DD + d;
    float tc = 0.f;
#pragma unroll 10
    for (int l = 0; l < KK; l++) tc += tas[l] * tcb[(size_t)l * BB * DD];
    float g = g_gate[b];
    g_mix[b * DD + d] = g * c + (1.0f - g) * tc;
}

// ------------------- readout + maxout -------------------
__global__ void readout_kernel(const float* __restrict__ RW, const float* __restrict__ Rb,
                               float* __restrict__ gout, int t) {
    int b = blockIdx.x;
    int nxt = (t & 1) ^ 1;
    __shared__ float xs[3 * DD];
    for (int i = threadIdx.x; i < DD; i += 128) {
        xs[i]          = g_emb[b * DD + i];
        xs[DD + i]     = g_h1[nxt][b * DD + i];
        xs[2 * DD + i] = g_mix[b * DD + i];
    }
    __syncthreads();
    int j = blockIdx.y * 128 + threadIdx.x;
    const float* w = RW + (size_t)j * (3 * DD);
    float acc = Rb[j];
#pragma unroll 2
    for (int k = 0; k < 3 * DD; k += 4) {
        float4 xv = *(const float4*)(xs + k);
        float4 wv = *(const float4*)(w + k);
        acc += xv.x * wv.x + xv.y * wv.y + xv.z * wv.z + xv.w * wv.w;
    }
    float other = __shfl_xor_sync(0xffffffffu, acc, 1);
    float mo = fmaxf(acc, other);
    if (!(j & 1)) gout[(size_t)t * BB * (DD / 2) + (size_t)b * (DD / 2) + (j >> 1)] = mo;
}

// ------------------- final state copy -------------------
__global__ void final_copy(float* __restrict__ hfin, float* __restrict__ mixfin) {
    int i = blockIdx.x * blockDim.x + threadIdx.x;
    if (i < BB * DD) {
        hfin[i]          = g_h0[0][i];  // after t=49, state parity index = 0
        hfin[BB * DD + i] = g_h1[0][i];
        mixfin[i]        = g_mix[i];
    }
}

// ------------------- launch -------------------
extern "C" void kernel_launch(void* const* d_in, const int* in_sizes, int n_in,
                              void* d_out, int out_size) {
    const int*   tgt      = (const int*)d_in[0];
    const float* hidden   = (const float*)d_in[1];
    const float* context  = (const float*)d_in[2];
    const float* smask    = (const float*)d_in[3];
    const float* tcontext = (const float*)d_in[4];
    const float* tmask    = (const float*)d_in[5];
    const float* mix_init = (const float*)d_in[6];
    const float* embt     = (const float*)d_in[7];
    const float* W_ih0    = (const float*)d_in[8];
    const float* W_hh0    = (const float*)d_in[9];
    const float* b_ih0    = (const float*)d_in[10];
    const float* b_hh0    = (const float*)d_in[11];
    const float* W_ih1    = (const float*)d_in[12];
    const float* W_hh1    = (const float*)d_in[13];
    const float* b_ih1    = (const float*)d_in[14];
    const float* b_hh1    = (const float*)d_in[15];
    const float* preW     = (const float*)d_in[16];
    const float* preB     = (const float*)d_in[17];
    const float* qW       = (const float*)d_in[18];
    const float* av       = (const float*)d_in[19];
    const float* tpreW    = (const float*)d_in[20];
    const float* tpreB    = (const float*)d_in[21];
    const float* tqW      = (const float*)d_in[22];
    const float* tav      = (const float*)d_in[23];
    const float* RW       = (const float*)d_in[24];
    const float* Rb       = (const float*)d_in[25];
    const float* gW       = (const float*)d_in[26];
    const float* gb       = (const float*)d_in[27];

    float* out   = (float*)d_out;
    float* go    = out;                                   // [T,B,256]
    float* hf    = go + (size_t)TT * BB * (DD / 2);       // [2,B,D]
    float* attn  = hf + 2 * BB * DD;                      // [T,B,S]
    float* tattn = attn + (size_t)TT * BB * SS;           // [T,B,K]
    float* mixf  = tattn + (size_t)TT * BB * KK;          // [B,D]
    float* gatev = mixf + BB * DD;                        // [T,B,1]

    init_state<<<(BB * DD + 255) / 256, 256>>>(hidden, mix_init);
    precompute_kernel<<<BB * SS, 128>>>(context, preW, preB, SS, 0);
    precompute_kernel<<<BB * KK, 128>>>(tcontext, tpreW, tpreB, KK, 1);

    for (int t = 0; t < TT; t++) {
        gru0_kernel<<<dim3(BB, 4), 128>>>(tgt, embt, W_ih0, W_hh0, b_ih0, b_hh0, t);
        gru1_kernel<<<dim3(BB, 4), 128>>>(W_ih1, W_hh1, b_ih1, b_hh1, t);
        qproj_kernel<<<dim3(BB, 8), 128>>>(qW, tqW, gW, gb, gatev, t);
        attn_kernel<<<dim3(BB, 2), 512>>>(av, tav, smask, tmask, attn, tattn, t);
        ctxmix_kernel<<<dim3(BB, 4), 128>>>(context, tcontext, attn, tattn, t);
        readout_kernel<<<dim3(BB, 4), 128>>>(RW, Rb, go, t);
    }
    final_copy<<<(BB * DD + 255) / 256, 256>>>(hf, mixf);
}

// round 2
// speedup vs baseline: 3.8621x; 3.8621x over previous
#include <cuda_runtime.h>

#define BBATCH 64
#define DDIM   512
#define TSTEPS 50
#define SLEN   400
#define KLEN   50

// ------------------- device scratch -------------------
__device__ float g_pre [BBATCH * SLEN * DDIM];   // [B][S][D]
__device__ float g_tpre[BBATCH * KLEN * DDIM];   // [B][K][D]
__device__ float g_pA[8 * 1536 * 64];            // GEMM partials (matrix a)
__device__ float g_pB[4 * 1536 * 64];            // GEMM partials (matrix b)
__device__ float g_x0[1024 * 64];                // [emb; mix_old]  transposed [K][B]
__device__ float g_xr[1536 * 64];                // [emb; h1; mix_new] transposed
__device__ float g_h0T[512 * 64];                // h0 transposed [D][B]
__device__ float g_qT [512 * 64];
__device__ float g_tqT[512 * 64];
__device__ float g_gate[64];

__device__ __forceinline__ float sigmoidf_(float x) { return 1.0f / (1.0f + __expf(-x)); }
__device__ __forceinline__ float tanh_fast(float x) {
    float y; asm("tanh.approx.f32 %0, %1;" : "=f"(y) : "f"(x)); return y;
}

__device__ __forceinline__ float* xptr(int c) {
    switch (c) {
        case 0:  return g_x0;
        case 1:  return g_h0T;
        case 2:  return g_xr + 512 * 64;   // h1T section
        default: return g_xr;
    }
}

// ------------------- init -------------------
__global__ void init_state(const float* __restrict__ hidden, const float* __restrict__ mix_init) {
    int idx = blockIdx.x * 256 + threadIdx.x;          // 32768
    int b = idx >> 9, d = idx & 511;
    g_h0T[d * 64 + b]            = hidden[idx];
    g_xr[(512 + d) * 64 + b]     = hidden[32768 + idx]; // h1T
    g_x0[(512 + d) * 64 + b]     = mix_init[idx];       // mix_old
}

// ------------------- big GEMM: pre = ctx @ W^T + b  -------------------
// grid.x = l (0..449), grid.y = mtile (0..3). 256 threads. K = 512 full.
__global__ void pre_gemm(const float* __restrict__ context, const float* __restrict__ tcontext,
                         const float* __restrict__ preW, const float* __restrict__ preB,
                         const float* __restrict__ tpreW, const float* __restrict__ tpreB) {
    __shared__ float Ws[32][132];
    __shared__ float Xs[32][64];
    int l = blockIdx.x;
    const float *ctx, *W, *bias; float* out; int L;
    if (l < SLEN) { ctx = context;  W = preW;  bias = preB;  out = g_pre;  L = SLEN; }
    else { l -= SLEN; ctx = tcontext; W = tpreW; bias = tpreB; out = g_tpre; L = KLEN; }
    int m0 = blockIdx.y * 128;
    int tid = threadIdx.x;
    int tm8 = (tid >> 4) * 8, tn4 = (tid & 15) * 4;
    float acc[8][4];
#pragma unroll
    for (int i = 0; i < 8; i++)
#pragma unroll
        for (int j = 0; j < 4; j++) acc[i][j] = 0.f;

    int wrow = tid >> 3, wk = (tid & 7) * 4;
    int xb = tid >> 2, xk = (tid & 3) * 8;
    const float* xbase = ctx + (size_t)l * 64 * 512;

    for (int s = 0; s < 512; s += 32) {
#pragma unroll
        for (int p = 0; p < 4; p++) {
            int m = p * 32 + wrow;
            float4 w = *(const float4*)(W + (size_t)(m0 + m) * 512 + s + wk);
            Ws[wk + 0][m] = w.x; Ws[wk + 1][m] = w.y; Ws[wk + 2][m] = w.z; Ws[wk + 3][m] = w.w;
        }
        {
            const float* cp = xbase + (size_t)xb * 512 + s + xk;
            float4 c0 = *(const float4*)(cp);
            float4 c1 = *(const float4*)(cp + 4);
            Xs[xk + 0][xb] = c0.x; Xs[xk + 1][xb] = c0.y; Xs[xk + 2][xb] = c0.z; Xs[xk + 3][xb] = c0.w;
            Xs[xk + 4][xb] = c1.x; Xs[xk + 5][xb] = c1.y; Xs[xk + 6][xb] = c1.z; Xs[xk + 7][xb] = c1.w;
        }
        __syncthreads();
#pragma unroll 8
        for (int k = 0; k < 32; k++) {
            float4 a0 = *(const float4*)&Ws[k][tm8];
            float4 a1 = *(const float4*)&Ws[k][tm8 + 4];
            float4 xv = *(const float4*)&Xs[k][tn4];
            float av[8] = {a0.x, a0.y, a0.z, a0.w, a1.x, a1.y, a1.z, a1.w};
            float xw[4] = {xv.x, xv.y, xv.z, xv.w};
#pragma unroll
            for (int i = 0; i < 8; i++)
#pragma unroll
                for (int j = 0; j < 4; j++) acc[i][j] = fmaf(av[i], xw[j], acc[i][j]);
        }
        __syncthreads();
    }
    // out[b][l][j], j contiguous per thread
#pragma unroll
    for (int jj = 0; jj < 4; jj++) {
        int b = tn4 + jj;
        float* op = out + ((size_t)b * L + l) * 512 + m0 + tm8;
        float4 v0 = {acc[0][jj] + bias[m0 + tm8 + 0], acc[1][jj] + bias[m0 + tm8 + 1],
                     acc[2][jj] + bias[m0 + tm8 + 2], acc[3][jj] + bias[m0 + tm8 + 3]};
        float4 v1 = {acc[4][jj] + bias[m0 + tm8 + 4], acc[5][jj] + bias[m0 + tm8 + 5],
                     acc[6][jj] + bias[m0 + tm8 + 6], acc[7][jj] + bias[m0 + tm8 + 7]};
        *(float4*)(op) = v0;
        *(float4*)(op + 4) = v1;
    }
}

// ------------------- per-step GEMM: P[kc][M][64] = W[M,K-chunk] @ X[K-chunk][64] -------------------
// Two matrices per launch. Matrix a -> g_pA, matrix b -> g_pB. Kchunk = 128 fixed.
__global__ void gemm2(const float* __restrict__ Wa, int xcA, int mtA, int kcA, int KA,
                      const float* __restrict__ Wb, int xcB, int mtB, int kcB, int KB) {
    __shared__ float Ws[32][132];
    __shared__ float Xs[32][64];
    int id = blockIdx.x;
    const float* W; const float* X; float* P; int mt, kc, K, mtiles;
    int nA = mtA * kcA;
    if (id < nA) { mt = id % mtA; kc = id / mtA; W = Wa; X = xptr(xcA); P = g_pA; K = KA; mtiles = mtA; }
    else { id -= nA; mt = id % mtB; kc = id / mtB; W = Wb; X = xptr(xcB); P = g_pB; K = KB; mtiles = mtB; }
    int m0 = mt * 128, k0 = kc * 128;
    int tid = threadIdx.x;
    int tm8 = (tid >> 4) * 8, tn4 = (tid & 15) * 4;
    float acc[8][4];
#pragma unroll
    for (int i = 0; i < 8; i++)
#pragma unroll
        for (int j = 0; j < 4; j++) acc[i][j] = 0.f;

    int wrow = tid >> 3, wk = (tid & 7) * 4;

    for (int s = 0; s < 128; s += 32) {
#pragma unroll
        for (int p = 0; p < 4; p++) {
            int m = p * 32 + wrow;
            float4 w = *(const float4*)(W + (size_t)(m0 + m) * K + k0 + s + wk);
            Ws[wk + 0][m] = w.x; Ws[wk + 1][m] = w.y; Ws[wk + 2][m] = w.z; Ws[wk + 3][m] = w.w;
        }
#pragma unroll
        for (int p = 0; p < 2; p++) {
            int f = p * 256 + tid;
            int r = f >> 4, c = (f & 15) * 4;
            *(float4*)&Xs[r][c] = *(const float4*)(X + (size_t)(k0 + s + r) * 64 + c);
        }
        __syncthreads();
#pragma unroll 8
        for (int k = 0; k < 32; k++) {
            float4 a0 = *(const float4*)&Ws[k][tm8];
            float4 a1 = *(const float4*)&Ws[k][tm8 + 4];
            float4 xv = *(const float4*)&Xs[k][tn4];
            float av[8] = {a0.x, a0.y, a0.z, a0.w, a1.x, a1.y, a1.z, a1.w};
            float xw[4] = {xv.x, xv.y, xv.z, xv.w};
#pragma unroll
            for (int i = 0; i < 8; i++)
#pragma unroll
                for (int j = 0; j < 4; j++) acc[i][j] = fmaf(av[i], xw[j], acc[i][j]);
        }
        __syncthreads();
    }
    float* pout = P + ((size_t)kc * mtiles * 128 + m0 + tm8) * 64 + tn4;
#pragma unroll
    for (int i = 0; i < 8; i++) {
        float4 v = {acc[i][0], acc[i][1], acc[i][2], acc[i][3]};
        *(float4*)(pout + (size_t)i * 64) = v;
    }
}

// ------------------- prep: embedding lookup into x0 / xr -------------------
__global__ void prep0(const int* __restrict__ tgt, const float* __restrict__ embt, int t) {
    int b = blockIdx.x;
    int k = blockIdx.y * 128 + threadIdx.x;
    int tok = tgt[t * 64 + b];
    float e = embt[(size_t)tok * 512 + k];
    g_x0[k * 64 + b] = e;
    g_xr[k * 64 + b] = e;
}

// ------------------- GRU activation (combine partials) -------------------
__global__ void gru_act(const float* __restrict__ b_ih, const float* __restrict__ b_hh,
                        int which, int kci, int kch) {
    int idx = blockIdx.x * 256 + threadIdx.x;   // 512*64
    int j = idx >> 6, b = idx & 63;
    float* hT = (which == 0) ? g_h0T : (g_xr + 512 * 64);
    float ir = b_ih[j], iz = b_ih[j + 512], in_ = b_ih[j + 1024];
    for (int kc = 0; kc < kci; kc++) {
        const float* p = g_pA + (size_t)kc * 1536 * 64;
        ir += p[j * 64 + b]; iz += p[(j + 512) * 64 + b]; in_ += p[(j + 1024) * 64 + b];
    }
    float hr = b_hh[j], hz = b_hh[j + 512], hn = b_hh[j + 1024];
    for (int kc = 0; kc < kch; kc++) {
        const float* p = g_pB + (size_t)kc * 1536 * 64;
        hr += p[j * 64 + b]; hz += p[(j + 512) * 64 + b]; hn += p[(j + 1024) * 64 + b];
    }
    float r = sigmoidf_(ir + hr);
    float z = sigmoidf_(iz + hz);
    float n = tanhf(in_ + r * hn);
    float h = hT[j * 64 + b];
    hT[j * 64 + b] = (1.f - z) * n + z * h;
}

// ------------------- q/tq combine -------------------
__global__ void actq() {
    int idx = blockIdx.x * 256 + threadIdx.x;   // 2*512*64
    int mat = idx >> 15;
    int r = idx & 32767;
    int j = r >> 6, b = r & 63;
    const float* p = mat ? g_pB : g_pA;
    float s = 0.f;
#pragma unroll
    for (int kc = 0; kc < 4; kc++) s += p[((size_t)kc * 512 + j) * 64 + b];
    (mat ? g_tqT : g_qT)[j * 64 + b] = s;
}

// ------------------- energy + softmax (+ gate in y==0) -------------------
__global__ void attn_kernel(const float* __restrict__ v, const float* __restrict__ tv,
                            const float* __restrict__ smask, const float* __restrict__ tmask,
                            float* __restrict__ attn_out, float* __restrict__ tattn_out,
                            const float* __restrict__ gW, const float* __restrict__ gb,
                            float* __restrict__ gate_out, int t) {
    int b = blockIdx.x;
    bool topic = (blockIdx.y == 1);
    int L = topic ? KLEN : SLEN;
    const float* pre = topic ? (g_tpre + (size_t)b * KLEN * 512) : (g_pre + (size_t)b * SLEN * 512);
    const float* qq  = topic ? g_tqT : g_qT;
    const float* vv  = topic ? tv : v;
    const float* mk  = topic ? (tmask + b * KLEN) : (smask + b * SLEN);
    float* aout = topic ? (tattn_out + (size_t)t * 64 * KLEN + (size_t)b * KLEN)
                        : (attn_out  + (size_t)t * 64 * SLEN + (size_t)b * SLEN);
    __shared__ float qs[512], vs[512], es[SLEN];
    __shared__ float sred[16];
    int tid = threadIdx.x, warp = tid >> 5, lane = tid & 31;

    if (!topic) {  // gate = sigmoid(h1 . gW)
        float gv = g_xr[(512 + tid) * 64 + b] * gW[tid];
#pragma unroll
        for (int o = 16; o; o >>= 1) gv += __shfl_xor_sync(0xffffffffu, gv, o);
        if (lane == 0) sred[warp] = gv;
        __syncthreads();
        if (tid == 0) {
            float s = 0.f;
#pragma unroll
            for (int w = 0; w < 16; w++) s += sred[w];
            float g = sigmoidf_(s + gb[0]);
            g_gate[b] = g;
            gate_out[t * 64 + b] = g;
        }
        __syncthreads();
    }

    qs[tid] = qq[tid * 64 + b];
    vs[tid] = vv[tid];
    __syncthreads();

    for (int l = warp; l < L; l += 16) {
        const float* pr = pre + (size_t)l * 512;
        float e = 0.f;
#pragma unroll
        for (int c = 0; c < 4; c++) {
            int a = c * 128 + lane * 4;
            float4 p  = *(const float4*)(pr + a);
            float4 q4 = *(const float4*)(qs + a);
            float4 v4 = *(const float4*)(vs + a);
            e += tanh_fast(p.x + q4.x) * v4.x;
            e += tanh_fast(p.y + q4.y) * v4.y;
            e += tanh_fast(p.z + q4.z) * v4.z;
            e += tanh_fast(p.w + q4.w) * v4.w;
        }
#pragma unroll
        for (int o = 16; o; o >>= 1) e += __shfl_xor_sync(0xffffffffu, e, o);
        if (lane == 0) es[l] = (mk[l] > 0.5f) ? -1e6f : e;
    }
    __syncthreads();
    float m = -3.4e38f;
    for (int i = tid; i < L; i += 512) m = fmaxf(m, es[i]);
#pragma unroll
    for (int o = 16; o; o >>= 1) m = fmaxf(m, __shfl_xor_sync(0xffffffffu, m, o));
    if (lane == 0) sred[warp] = m;
    __syncthreads();
    float bm = sred[0];
#pragma unroll
    for (int w = 1; w < 16; w++) bm = fmaxf(bm, sred[w]);
    __syncthreads();
    float s = 0.f;
    for (int i = tid; i < L; i += 512) {
        float ex = __expf(es[i] - bm);
        es[i] = ex;
        s += ex;
    }
#pragma unroll
    for (int o = 16; o; o >>= 1) s += __shfl_xor_sync(0xffffffffu, s, o);
    if (lane == 0) sred[warp] = s;
    __syncthreads();
    float bs = 0.f;
#pragma unroll
    for (int w = 0; w < 16; w++) bs += sred[w];
    float inv = 1.0f / bs;
    for (int i = tid; i < L; i += 512) aout[i] = es[i] * inv;
}

// ------------------- weighted contexts + gated mix (writes transposed) -------------------
__global__ void ctxmix_kernel(const float* __restrict__ context, const float* __restrict__ tcontext,
                              const float* __restrict__ attn_out, const float* __restrict__ tattn_out,
                              int t) {
    int b = blockIdx.x;
    int d = blockIdx.y * 128 + threadIdx.x;
    __shared__ float as[SLEN];
    __shared__ float tas[KLEN];
    const float* a  = attn_out  + (size_t)t * 64 * SLEN + (size_t)b * SLEN;
    const float* ta = tattn_out + (size_t)t * 64 * KLEN + (size_t)b * KLEN;
    for (int i = threadIdx.x; i < SLEN; i += 128) as[i] = a[i];
    for (int i = threadIdx.x; i < KLEN; i += 128) tas[i] = ta[i];
    __syncthreads();
    const float* cb = context + (size_t)b * 512 + d;
    float c = 0.f;
#pragma unroll 8
    for (int l = 0; l < SLEN; l++) c += as[l] * cb[(size_t)l * 64 * 512];
    const float* tcb = tcontext + (size_t)b * 512 + d;
    float tc = 0.f;
#pragma unroll 10
    for (int l = 0; l < KLEN; l++) tc += tas[l] * tcb[(size_t)l * 64 * 512];
    float g = g_gate[b];
    float mixv = g * c + (1.f - g) * tc;
    g_x0[(512 + d) * 64 + b]  = mixv;   // for next step's GRU0 input
    g_xr[(1024 + d) * 64 + b] = mixv;   // for this step's readout
}

// ------------------- readout combine + maxout -------------------
__global__ void actD(const float* __restrict__ Rb, float* __restrict__ gout, int t) {
    int idx = blockIdx.x * 256 + threadIdx.x;   // 256*64
    int u = idx >> 6, b = idx & 63;
    int j0 = 2 * u, j1 = 2 * u + 1;
    float r0 = Rb[j0], r1 = Rb[j1];
#pragma unroll
    for (int kc = 0; kc < 12; kc++) {
        const float* p = g_pA + (size_t)kc * 512 * 64;
        r0 += p[j0 * 64 + b];
        r1 += p[j1 * 64 + b];
    }
    gout[(size_t)t * 16384 + b * 256 + u] = fmaxf(r0, r1);
}

// ------------------- final state copy (transpose back) -------------------
__global__ void final_copy(float* __restrict__ hfin, float* __restrict__ mixfin) {
    int idx = blockIdx.x * 256 + threadIdx.x;   // 32768
    int b = idx >> 9, d = idx & 511;
    hfin[idx]          = g_h0T[d * 64 + b];
    hfin[32768 + idx]  = g_xr[(512 + d) * 64 + b];
    mixfin[idx]        = g_x0[(512 + d) * 64 + b];
}

// ------------------- launch -------------------
extern "C" void kernel_launch(void* const* d_in, const int* in_sizes, int n_in,
                              void* d_out, int out_size) {
    const int*   tgt      = (const int*)d_in[0];
    const float* hidden   = (const float*)d_in[1];
    const float* context  = (const float*)d_in[2];
    const float* smask    = (const float*)d_in[3];
    const float* tcontext = (const float*)d_in[4];
    const float* tmask    = (const float*)d_in[5];
    const float* mix_init = (const float*)d_in[6];
    const float* embt     = (const float*)d_in[7];
    const float* W_ih0    = (const float*)d_in[8];
    const float* W_hh0    = (const float*)d_in[9];
    const float* b_ih0    = (const float*)d_in[10];
    const float* b_hh0    = (const float*)d_in[11];
    const float* W_ih1    = (const float*)d_in[12];
    const float* W_hh1    = (const float*)d_in[13];
    const float* b_ih1    = (const float*)d_in[14];
    const float* b_hh1    = (const float*)d_in[15];
    const float* preW     = (const float*)d_in[16];
    const float* preB     = (const float*)d_in[17];
    const float* qW       = (const float*)d_in[18];
    const float* av       = (const float*)d_in[19];
    const float* tpreW    = (const float*)d_in[20];
    const float* tpreB    = (const float*)d_in[21];
    const float* tqW      = (const float*)d_in[22];
    const float* tav      = (const float*)d_in[23];
    const float* RW       = (const float*)d_in[24];
    const float* Rb       = (const float*)d_in[25];
    const float* gW       = (const float*)d_in[26];
    const float* gb       = (const float*)d_in[27];

    float* out   = (float*)d_out;
    float* go    = out;                                   // [T,B,256]
    float* hf    = go + (size_t)TSTEPS * 64 * 256;        // [2,B,D]
    float* attn  = hf + 2 * 64 * 512;                     // [T,B,S]
    float* tattn = attn + (size_t)TSTEPS * 64 * SLEN;     // [T,B,K]
    float* mixf  = tattn + (size_t)TSTEPS * 64 * KLEN;    // [B,D]
    float* gatev = mixf + 64 * 512;                       // [T,B,1]

    init_state<<<128, 256>>>(hidden, mix_init);
    pre_gemm<<<dim3(SLEN + KLEN, 4), 256>>>(context, tcontext, preW, preB, tpreW, tpreB);

    for (int t = 0; t < TSTEPS; t++) {
        prep0<<<dim3(64, 4), 128>>>(tgt, embt, t);
        // GRU0: gi0 = W_ih0 @ x0 (K=1024, 8 chunks), gh0 = W_hh0 @ h0T (K=512, 4 chunks)
        gemm2<<<144, 256>>>(W_ih0, 0, 12, 8, 1024, W_hh0, 1, 12, 4, 512);
        gru_act<<<128, 256>>>(b_ih0, b_hh0, 0, 8, 4);
        // GRU1: gi1 = W_ih1 @ h0T_new, gh1 = W_hh1 @ h1T_old
        gemm2<<<96, 256>>>(W_ih1, 1, 12, 4, 512, W_hh1, 2, 12, 4, 512);
        gru_act<<<128, 256>>>(b_ih1, b_hh1, 1, 4, 4);
        // q / tq projections
        gemm2<<<32, 256>>>(qW, 2, 4, 4, 512, tqW, 2, 4, 4, 512);
        actq<<<256, 256>>>();
        attn_kernel<<<dim3(64, 2), 512>>>(av, tav, smask, tmask, attn, tattn, gW, gb, gatev, t);
        ctxmix_kernel<<<dim3(64, 4), 128>>>(context, tcontext, attn, tattn, t);
        // readout: M=512, K=1536 (12 chunks), X = [emb; h1; mix_new]
        gemm2<<<48, 256>>>(RW, 3, 4, 12, 1536, RW, 3, 0, 0, 512);
        actD<<<64, 256>>>(Rb, go, t);
    }
    final_copy<<<128, 256>>>(hf, mixf);
}